// round 2
// baseline (speedup 1.0000x reference)
#include <cuda_runtime.h>
#include <math.h>

// PyTorchCG: BS=64, N=1024, maxiter derived from out_size.
#define CG_N  1024
#define CG_BS 64
#define TS    128                 // symmetric tile size
#define NT    (CG_N / TS)         // 8 tiles per dim
#define NPAIR (NT * (NT + 1) / 2) // 36 unique tile pairs

// Persistent CG state (no allocs allowed -> __device__ globals).
__device__ float g_r  [CG_BS * CG_N];
__device__ float g_p  [CG_BS * CG_N];
__device__ float g_Ap [CG_BS * CG_N];
__device__ float g_d  [CG_BS * CG_N];   // diag(M_inv)
__device__ float g_rz [CG_BS];
__device__ float g_pap[CG_BS];

// ---------------------------------------------------------------------------
// Zero the accumulators before the very first matvec.
// ---------------------------------------------------------------------------
__global__ void k_zero()
{
    const int b = blockIdx.x, tid = threadIdx.x;
    float4 z = make_float4(0.f, 0.f, 0.f, 0.f);
#pragma unroll
    for (int k = 0; k < CG_N / 1024; ++k)
        reinterpret_cast<float4*>(g_Ap + (size_t)b * CG_N)[tid + 256 * k] = z;
    if (tid == 0) g_pap[b] = 0.f;
}

// ---------------------------------------------------------------------------
// Symmetric batched matvec: g_Ap[b] += A[b] @ v[b], exploiting A = A^T.
// One CTA per unique 128x128 tile pair (bi<=bj) per batch: 36*64 CTAs.
// Off-diagonal tiles are read ONCE and applied to both y_bi (row dots) and
// y_bj (transpose column sums) -> 56.25% of full-matrix traffic.
// Also accumulates p.Ap into g_pap[b] (off-diag tiles count twice).
// v == nullptr means "use g_p".  g_Ap / g_pap must be zero on entry.
// ---------------------------------------------------------------------------
__global__ void k_symmv(const float* __restrict__ A, const float* __restrict__ v)
{
    const int b   = blockIdx.y;
    const int tid = threadIdx.x;

    // decode linear pair index -> (bi, bj) with bi <= bj
    int li = blockIdx.x, bi = 0;
    while (li >= NT - bi) { li -= NT - bi; ++bi; }
    const int  bj   = bi + li;
    const bool diag = (bi == bj);

    __shared__ float spi[TS];        // v segment bi
    __shared__ float spj[TS];        // v segment bj
    __shared__ float scol[8][TS];    // cross-warp column-sum reduce

    const float* vb = (v != nullptr) ? (v + (size_t)b * CG_N)
                                     : (g_p + (size_t)b * CG_N);
    if (tid < TS / 4)
        reinterpret_cast<float4*>(spi)[tid] =
            reinterpret_cast<const float4*>(vb + bi * TS)[tid];
    else if (tid < TS / 2)
        reinterpret_cast<float4*>(spj)[tid - TS / 4] =
            reinterpret_cast<const float4*>(vb + bj * TS)[tid - TS / 4];
    __syncthreads();

    const int warp = tid >> 5;
    const int lane = tid & 31;

    const float4* Abase = reinterpret_cast<const float4*>(
        A + ((size_t)b * CG_N + (size_t)bi * TS) * CG_N + (size_t)bj * TS);
    const int rstride = CG_N / 4;    // float4 per matrix row

    const float4 pj4  = reinterpret_cast<const float4*>(spj)[lane]; // cols 4l..4l+3
    float4 cacc = make_float4(0.f, 0.f, 0.f, 0.f);
    float  pap_part = 0.f;
    float* yrow = g_Ap + (size_t)b * CG_N + (size_t)bi * TS;

#pragma unroll 4
    for (int rr = 0; rr < TS / 8; ++rr) {        // 16 rows per warp
        const int r = warp + 8 * rr;
        float4 a = Abase[(size_t)r * rstride + lane];   // A[bi*TS+r, bj*TS+4l..]
        // row part: d = A[r,:] . p_j
        float d = a.x * pj4.x + a.y * pj4.y + a.z * pj4.z + a.w * pj4.w;
#pragma unroll
        for (int off = 16; off; off >>= 1)
            d += __shfl_xor_sync(0xffffffffu, d, off);
        // transpose part: col accumulators += A[r,c] * p_i[r]
        const float pir = spi[r];
        cacc.x += a.x * pir;  cacc.y += a.y * pir;
        cacc.z += a.z * pir;  cacc.w += a.w * pir;
        if (lane == 0) {
            atomicAdd(&yrow[r], d);
            pap_part += d * pir;                 // p_i^T A_tile p_j partial
        }
    }
    if (lane == 0)
        atomicAdd(&g_pap[b], diag ? pap_part : 2.f * pap_part);

    if (!diag) {   // uniform branch per CTA
        scol[warp][4 * lane + 0] = cacc.x;
        scol[warp][4 * lane + 1] = cacc.y;
        scol[warp][4 * lane + 2] = cacc.z;
        scol[warp][4 * lane + 3] = cacc.w;
        __syncthreads();
        if (tid < TS) {
            float s = 0.f;
#pragma unroll
            for (int w = 0; w < 8; ++w) s += scol[w][tid];
            atomicAdd(&g_Ap[(size_t)b * CG_N + (size_t)bj * TS + tid], s);
        }
    }
}

// ---------------------------------------------------------------------------
// Deterministic block-wide sum over 256 threads.
// ---------------------------------------------------------------------------
__device__ __forceinline__ float block_sum(float v, float* sbuf)
{
    const int tid = threadIdx.x;
#pragma unroll
    for (int off = 16; off; off >>= 1)
        v += __shfl_xor_sync(0xffffffffu, v, off);
    if ((tid & 31) == 0) sbuf[tid >> 5] = v;
    __syncthreads();
    if (tid < 8) {
        float w = sbuf[tid];
#pragma unroll
        for (int off = 4; off; off >>= 1)
            w += __shfl_xor_sync(0x000000ffu, w, off);
        if (tid == 0) sbuf[0] = w;
    }
    __syncthreads();
    float r = sbuf[0];
    __syncthreads();
    return r;
}

// ---------------------------------------------------------------------------
// Init: diag extract, r0 = b - A@x0 (g_Ap), z0 = d*r0, p0 = z0, rz0, ||r0||.
// Also re-zeroes g_Ap / g_pap for the first loop matvec.  grid=BS, block=256.
// ---------------------------------------------------------------------------
__global__ void k_init(const float* __restrict__ Minv,
                       const float* __restrict__ bvec,
                       float* __restrict__ out, int ldout)
{
    __shared__ float sbuf[8];
    const int b   = blockIdx.x;
    const int tid = threadIdx.x;
    const float* Mb = Minv + (size_t)b * CG_N * CG_N;

    float rz_p = 0.f, rr_p = 0.f;
#pragma unroll
    for (int k = 0; k < CG_N / 256; ++k) {
        const int    i  = tid + 256 * k;
        const size_t gi = (size_t)b * CG_N + i;
        float dv = Mb[(size_t)i * CG_N + i];
        float rv = bvec[gi] - g_Ap[gi];
        g_Ap[gi] = 0.f;                       // zero for next symmv
        float zv = dv * rv;
        g_d[gi] = dv;
        g_r[gi] = rv;
        g_p[gi] = zv;
        rz_p += rv * zv;
        rr_p += rv * rv;
    }
    float rz = block_sum(rz_p, sbuf);
    float rr = block_sum(rr_p, sbuf);
    if (tid == 0) {
        g_rz[b]  = rz;
        g_pap[b] = 0.f;
        out[(size_t)b * ldout] = sqrtf(rr);
    }
}

// ---------------------------------------------------------------------------
// CG update after g_Ap = A@p (and g_pap = p.Ap from the matvec epilogue):
//   alpha = rz/pAp; r -= alpha*Ap; z = d*r; beta = rz_new/rz; p = z + beta*p.
// Zeroes g_Ap / g_pap in place for the next iteration.  grid=BS, block=256.
// ---------------------------------------------------------------------------
__global__ void k_update(float* __restrict__ out, int it, int ldout)
{
    __shared__ float sbuf[8];
    const int b   = blockIdx.x;
    const int tid = threadIdx.x;

    const float rz_old = g_rz[b];
    const float pAp    = g_pap[b];
    const float alpha  = rz_old / pAp;

    float pv[4], rv[4], dv[4];
    float rz_p = 0.f, rr_p = 0.f;
#pragma unroll
    for (int k = 0; k < 4; ++k) {
        const size_t i = (size_t)b * CG_N + tid + 256 * k;
        const float ap = g_Ap[i];
        g_Ap[i] = 0.f;                        // zero for next symmv
        pv[k] = g_p[i];
        dv[k] = g_d[i];
        rv[k] = g_r[i] - alpha * ap;
        g_r[i] = rv[k];
        const float zv = dv[k] * rv[k];
        rz_p += rv[k] * zv;
        rr_p += rv[k] * rv[k];
    }
    const float rz_new = block_sum(rz_p, sbuf);
    const float rr     = block_sum(rr_p, sbuf);
    const float beta   = rz_new / rz_old;

#pragma unroll
    for (int k = 0; k < 4; ++k) {
        const size_t i = (size_t)b * CG_N + tid + 256 * k;
        g_p[i] = dv[k] * rv[k] + beta * pv[k];
    }

    if (tid == 0) {
        g_rz[b]  = rz_new;
        g_pap[b] = 0.f;
        out[(size_t)b * ldout + it + 1] = sqrtf(rr);
    }
}

// ---------------------------------------------------------------------------
// kernel_launch: graph-capturable kernel sequence.
// Inputs: A, b, x0, M_inv, rtol (unused by reference scan), maxiter.
// ---------------------------------------------------------------------------
extern "C" void kernel_launch(void* const* d_in, const int* in_sizes, int n_in,
                              void* d_out, int out_size)
{
    const float* A    = (const float*)d_in[0];
    const float* bvec = (const float*)d_in[1];
    const float* x0   = (const float*)d_in[2];
    const float* Minv = (const float*)d_in[3];
    float* out        = (float*)d_out;

    const int ldout   = out_size / CG_BS;   // maxiter + 1
    const int maxiter = ldout - 1;

    dim3 grid_mv(NPAIR, CG_BS);             // 36 x 64 = 2304 CTAs

    k_zero<<<CG_BS, 256>>>();
    k_symmv<<<grid_mv, 256>>>(A, x0);       // g_Ap = A @ x0
    k_init <<<CG_BS, 256>>>(Minv, bvec, out, ldout);

    for (int it = 0; it < maxiter; ++it) {
        k_symmv<<<grid_mv, 256>>>(A, nullptr);   // g_Ap = A @ p, g_pap = p.Ap
        k_update<<<CG_BS, 256>>>(out, it, ldout);
    }
}